// round 1
// baseline (speedup 1.0000x reference)
#include <cuda_runtime.h>
#include <cuda_bf16.h>

// DetectionLoss: sparse evaluation. Only cells hit by targets contribute to
// either loss term, so we never touch the dense pred tensors except at the
// ~3840 scattered cells per scale.

#define NCH   11
#define NCLS  6
#define NT    60
#define NB    64

// Per-scale accumulators (scratch via __device__ globals — no allocation).
__device__ float g_cls_sum[3];
__device__ float g_iou_sum[3];
__device__ float g_inner_sum[3];
__device__ int   g_npos[3];

__global__ void dl_init_kernel() {
    int i = threadIdx.x;
    if (i < 3) {
        g_cls_sum[i]   = 0.0f;
        g_iou_sum[i]   = 0.0f;
        g_inner_sum[i] = 0.0f;
        g_npos[i]      = 0;
    }
}

__device__ __forceinline__ float iou_scaled(
    float px, float py, float pw, float ph,
    float tx, float ty, float tw, float th, float sc)
{
    float pw2 = pw * sc * 0.5f, ph2 = ph * sc * 0.5f;
    float tw2 = tw * sc * 0.5f, th2 = th * sc * 0.5f;
    float x11 = px - pw2, x12 = px + pw2;
    float y11 = py - ph2, y12 = py + ph2;
    float x21 = tx - tw2, x22 = tx + tw2;
    float y21 = ty - th2, y22 = ty + th2;
    float iw = fmaxf(fminf(x12, x22) - fmaxf(x11, x21), 0.0f);
    float ih = fmaxf(fminf(y12, y22) - fmaxf(y11, y21), 0.0f);
    float inter = iw * ih;
    float a1 = (x12 - x11) * (y12 - y11);
    float a2 = (x22 - x21) * (y22 - y21);
    return inter / (a1 + a2 - inter + 1e-7f);
}

// grid = (NB, 3), block = 64 threads. Block (b, s) handles batch b at scale s.
__global__ void dl_main_kernel(
    const float* __restrict__ p3,
    const float* __restrict__ p4,
    const float* __restrict__ p5,
    const int*   __restrict__ tcls,
    const float* __restrict__ tbox)
{
    const int b   = blockIdx.x;
    const int s   = blockIdx.y;
    const int tid = threadIdx.x;

    const float* pred;
    int W;
    if      (s == 0) { pred = p3; W = 160; }
    else if (s == 1) { pred = p4; W = 80;  }
    else             { pred = p5; W = 40;  }
    const int H = W;

    __shared__ int   s_cls[NT];
    __shared__ float s_box[NT][4];
    __shared__ int   s_cell[NT];

    if (tid < NT) {
        s_cls[tid] = tcls[b * NT + tid];
        float4 bx = reinterpret_cast<const float4*>(tbox)[b * NT + tid];
        s_box[tid][0] = bx.x; s_box[tid][1] = bx.y;
        s_box[tid][2] = bx.z; s_box[tid][3] = bx.w;
        int gx = (int)(bx.x * (float)W); gx = min(max(gx, 0), W - 1);
        int gy = (int)(bx.y * (float)H); gy = min(max(gy, 0), H - 1);
        s_cell[tid] = gy * W + gx;
    }
    __syncthreads();

    float cls_p = 0.0f, iou_p = 0.0f, inner_p = 0.0f;
    int   np = 0;

    if (tid < NT) {
        const int cell = s_cell[tid];

        // Owner = LAST target mapping to this cell (XLA scatter: last write
        // wins for box_target / pos_mask).
        bool owner = true;
        for (int t2 = tid + 1; t2 < NT; ++t2)
            if (s_cell[t2] == cell) { owner = false; break; }

        if (owner) {
            // cls_target is the UNION of one-hots over all colliding targets
            // (different class channels are distinct scatter elements).
            unsigned cm = 0u;
            for (int t2 = 0; t2 < NT; ++t2)
                if (s_cell[t2] == cell) cm |= 1u << s_cls[t2];

            const size_t HW = (size_t)H * (size_t)W;
            const float* base = pred + (size_t)b * NCH * HW + (size_t)cell;

            // BCE over the 6 class channels vs multi-hot target.
            float bce = 0.0f;
            #pragma unroll
            for (int c = 0; c < NCLS; ++c) {
                float z = base[(size_t)c * HW];
                float t = ((cm >> c) & 1u) ? 1.0f : 0.0f;
                bce += fmaxf(z, 0.0f) - z * t + log1pf(expf(-fabsf(z)));
            }

            // Box channels are NCLS+1 .. NCLS+4 (channel 6 is skipped).
            float px = base[(size_t)7  * HW];
            float py = base[(size_t)8  * HW];
            float pw = base[(size_t)9  * HW];
            float ph = base[(size_t)10 * HW];

            float tx = s_box[tid][0], ty = s_box[tid][1];
            float tw = s_box[tid][2], th = s_box[tid][3];

            float iou   = iou_scaled(px, py, pw, ph, tx, ty, tw, th, 1.0f);
            float inner = iou_scaled(px, py, pw, ph, tx, ty, tw, th, 0.7f);

            cls_p   = bce;
            iou_p   = 1.0f - iou;
            inner_p = 1.0f - inner;
            np      = 1;
        }
    }

    // Warp reduction (block = 2 warps), then atomic into per-scale globals.
    #pragma unroll
    for (int o = 16; o > 0; o >>= 1) {
        cls_p   += __shfl_down_sync(0xffffffffu, cls_p,   o);
        iou_p   += __shfl_down_sync(0xffffffffu, iou_p,   o);
        inner_p += __shfl_down_sync(0xffffffffu, inner_p, o);
        np      += __shfl_down_sync(0xffffffffu, np,      o);
    }
    if ((tid & 31) == 0) {
        atomicAdd(&g_cls_sum[s],   cls_p);
        atomicAdd(&g_iou_sum[s],   iou_p);
        atomicAdd(&g_inner_sum[s], inner_p);
        atomicAdd(&g_npos[s],      np);
    }
}

__global__ void dl_final_kernel(float* __restrict__ out) {
    if (threadIdx.x == 0 && blockIdx.x == 0) {
        float cls_total = 0.0f, box_total = 0.0f;
        #pragma unroll
        for (int s = 0; s < 3; ++s) {
            float inv = 1.0f / ((float)g_npos[s] + 1e-8f);
            float cls_loss   = g_cls_sum[s]   * inv;
            float iou_term   = g_iou_sum[s]   * inv;
            float inner_term = g_inner_sum[s] * inv;
            // box_loss = 0.5*iou + 0.5*(0.5*iou + 0.5*inner)
            box_total += 0.75f * iou_term + 0.25f * inner_term;
            cls_total += cls_loss;
        }
        cls_total *= (1.0f / 3.0f);
        box_total *= (1.0f / 3.0f);
        out[0] = 0.5f * cls_total + 7.5f * box_total;  // CLS_W, BOX_W
        out[1] = cls_total;
        out[2] = box_total;
    }
}

extern "C" void kernel_launch(void* const* d_in, const int* in_sizes, int n_in,
                              void* d_out, int out_size)
{
    const float* p3   = (const float*)d_in[0];
    const float* p4   = (const float*)d_in[1];
    const float* p5   = (const float*)d_in[2];
    const int*   tcls = (const int*)  d_in[3];
    const float* tbox = (const float*)d_in[4];
    float*       out  = (float*)d_out;

    dl_init_kernel<<<1, 32>>>();
    dim3 grid(NB, 3);
    dl_main_kernel<<<grid, 64>>>(p3, p4, p5, tcls, tbox);
    dl_final_kernel<<<1, 32>>>(out);
}

// round 3
// speedup vs baseline: 1.9805x; 1.9805x over previous
#include <cuda_runtime.h>
#include <cuda_bf16.h>

// DetectionLoss, fully fused single kernel.
// Sparse evaluation: only target-hit cells contribute. Grid (64 batches x 3
// scales), 64 threads/block. Last block (fence+counter) finalizes the 3
// outputs and resets accumulators to zero for the next graph replay.

#define NCH   11
#define NCLS  6
#define NT    60
#define NB    64
#define NBLK  (NB * 3)

__device__ float    g_cls_sum[3];
__device__ float    g_iou_sum[3];
__device__ float    g_inner_sum[3];
__device__ float    g_npos[3];
__device__ unsigned g_done;

__device__ __forceinline__ float iou_scaled(
    float px, float py, float pw, float ph,
    float tx, float ty, float tw, float th, float sc)
{
    float pw2 = pw * sc * 0.5f, ph2 = ph * sc * 0.5f;
    float tw2 = tw * sc * 0.5f, th2 = th * sc * 0.5f;
    float x11 = px - pw2, x12 = px + pw2;
    float y11 = py - ph2, y12 = py + ph2;
    float x21 = tx - tw2, x22 = tx + tw2;
    float y21 = ty - th2, y22 = ty + th2;
    float iw = fmaxf(fminf(x12, x22) - fmaxf(x11, x21), 0.0f);
    float ih = fmaxf(fminf(y12, y22) - fmaxf(y11, y21), 0.0f);
    float inter = iw * ih;
    float a1 = (x12 - x11) * (y12 - y11);
    float a2 = (x22 - x21) * (y22 - y21);
    return inter / (a1 + a2 - inter + 1e-7f);
}

__global__ void __launch_bounds__(64, 16) dl_fused_kernel(
    const float* __restrict__ p3,
    const float* __restrict__ p4,
    const float* __restrict__ p5,
    const int*   __restrict__ tcls,
    const float* __restrict__ tbox,
    float*       __restrict__ out)
{
    const int b   = blockIdx.x;
    const int s   = blockIdx.y;
    const int tid = threadIdx.x;

    const float* pred;
    int W;
    if      (s == 0) { pred = p3; W = 160; }
    else if (s == 1) { pred = p4; W = 80;  }
    else             { pred = p5; W = 40;  }

    __shared__ int   s_cls[NT];
    __shared__ int   s_cell[NT];
    __shared__ float s_part[4][2];   // [metric][warp]

    float tx = 0.f, ty = 0.f, tw = 0.f, th = 0.f;
    int   cell = -1;

    // Pred values, loaded early (before any smem dependency) so all 10 DRAM
    // accesses are in flight during the collision scans.
    float z[NCLS], px = 0.f, py = 0.f, pw = 0.f, ph = 0.f;

    if (tid < NT) {
        s_cls[tid] = tcls[b * NT + tid];
        float4 bx = reinterpret_cast<const float4*>(tbox)[b * NT + tid];
        tx = bx.x; ty = bx.y; tw = bx.z; th = bx.w;
        int gx = (int)(tx * (float)W); gx = min(max(gx, 0), W - 1);
        int gy = (int)(ty * (float)W); gy = min(max(gy, 0), W - 1);
        cell = gy * W + gx;
        s_cell[tid] = cell;

        const size_t HW   = (size_t)W * (size_t)W;
        const float* base = pred + (size_t)b * NCH * HW + (size_t)cell;
        #pragma unroll
        for (int c = 0; c < NCLS; ++c) z[c] = __ldg(base + (size_t)c * HW);
        px = __ldg(base + (size_t)7  * HW);
        py = __ldg(base + (size_t)8  * HW);
        pw = __ldg(base + (size_t)9  * HW);
        ph = __ldg(base + (size_t)10 * HW);
    }
    __syncthreads();

    float cls_p = 0.0f, iou_p = 0.0f, inner_p = 0.0f, np = 0.0f;

    if (tid < NT) {
        // Owner = LAST target mapping to this cell (scatter: last write wins).
        bool owner = true;
        #pragma unroll 4
        for (int t2 = tid + 1; t2 < NT; ++t2)
            if (s_cell[t2] == cell) { owner = false; break; }

        if (owner) {
            // cls target = union of one-hots over all colliding targets.
            unsigned cm = 0u;
            #pragma unroll 4
            for (int t2 = 0; t2 < NT; ++t2)
                if (s_cell[t2] == cell) cm |= 1u << s_cls[t2];

            float bce = 0.0f;
            #pragma unroll
            for (int c = 0; c < NCLS; ++c) {
                float t = ((cm >> c) & 1u) ? 1.0f : 0.0f;
                bce += fmaxf(z[c], 0.0f) - z[c] * t + log1pf(expf(-fabsf(z[c])));
            }

            float iou   = iou_scaled(px, py, pw, ph, tx, ty, tw, th, 1.0f);
            float inner = iou_scaled(px, py, pw, ph, tx, ty, tw, th, 0.7f);

            cls_p = bce;  iou_p = 1.0f - iou;  inner_p = 1.0f - inner;  np = 1.0f;
        }
    }

    // Warp reduce, then combine the 2 warps in smem.
    #pragma unroll
    for (int o = 16; o > 0; o >>= 1) {
        cls_p   += __shfl_down_sync(0xffffffffu, cls_p,   o);
        iou_p   += __shfl_down_sync(0xffffffffu, iou_p,   o);
        inner_p += __shfl_down_sync(0xffffffffu, inner_p, o);
        np      += __shfl_down_sync(0xffffffffu, np,      o);
    }
    const int warp = tid >> 5;
    if ((tid & 31) == 0) {
        s_part[0][warp] = cls_p;  s_part[1][warp] = iou_p;
        s_part[2][warp] = inner_p; s_part[3][warp] = np;
    }
    __syncthreads();

    bool last = false;
    if (tid == 0) {
        atomicAdd(&g_cls_sum[s],   s_part[0][0] + s_part[0][1]);
        atomicAdd(&g_iou_sum[s],   s_part[1][0] + s_part[1][1]);
        atomicAdd(&g_inner_sum[s], s_part[2][0] + s_part[2][1]);
        atomicAdd(&g_npos[s],      s_part[3][0] + s_part[3][1]);
        __threadfence();
        unsigned done = atomicAdd(&g_done, 1u);
        last = (done == NBLK - 1);
    }

    if (last) {
        float cls_total = 0.0f, box_total = 0.0f;
        #pragma unroll
        for (int k = 0; k < 3; ++k) {
            // atomic reads bypass L1 (values were written by L2 atomics).
            float npos  = atomicAdd(&g_npos[k],      0.0f);
            float csum  = atomicAdd(&g_cls_sum[k],   0.0f);
            float isum  = atomicAdd(&g_iou_sum[k],   0.0f);
            float insum = atomicAdd(&g_inner_sum[k], 0.0f);
            float inv = 1.0f / (npos + 1e-8f);
            cls_total += csum * inv;
            // box_loss = 0.5*iou + 0.5*(0.5*iou + 0.5*inner)
            box_total += 0.75f * (isum * inv) + 0.25f * (insum * inv);
        }
        cls_total *= (1.0f / 3.0f);
        box_total *= (1.0f / 3.0f);
        out[0] = 0.5f * cls_total + 7.5f * box_total;  // CLS_W, BOX_W
        out[1] = cls_total;
        out[2] = box_total;

        // Reset for next replay (deterministic across graph launches).
        #pragma unroll
        for (int k = 0; k < 3; ++k) {
            atomicExch(&g_cls_sum[k],   0.0f);
            atomicExch(&g_iou_sum[k],   0.0f);
            atomicExch(&g_inner_sum[k], 0.0f);
            atomicExch(&g_npos[k],      0.0f);
        }
        atomicExch(&g_done, 0u);
    }
}

extern "C" void kernel_launch(void* const* d_in, const int* in_sizes, int n_in,
                              void* d_out, int out_size)
{
    const float* p3   = (const float*)d_in[0];
    const float* p4   = (const float*)d_in[1];
    const float* p5   = (const float*)d_in[2];
    const int*   tcls = (const int*)  d_in[3];
    const float* tbox = (const float*)d_in[4];
    float*       out  = (float*)d_out;

    dim3 grid(NB, 3);
    dl_fused_kernel<<<grid, 64>>>(p3, p4, p5, tcls, tbox, out);
}

// round 5
// speedup vs baseline: 4.2507x; 2.1463x over previous
#include <cuda_runtime.h>
#include <cuda_bf16.h>

// DetectionLoss, single fused kernel, v3.
// Grid: 64 blocks (one per batch) x 192 threads (3 scales x 64).
// Sparse evaluation; register-resident collision scan; contention-free
// partial-sum writes + last-block parallel reduction (no accumulator atomics).

#define NCH   11
#define NCLS  6
#define NT    60
#define NB    64

__device__ float    g_part[NB][12];   // [block][scale*4 + {cls,iou,inner,np}]
__device__ unsigned g_done;

__device__ __forceinline__ float iou_scaled(
    float px, float py, float pw, float ph,
    float tx, float ty, float tw, float th, float sc)
{
    float pw2 = pw * sc * 0.5f, ph2 = ph * sc * 0.5f;
    float tw2 = tw * sc * 0.5f, th2 = th * sc * 0.5f;
    float x11 = px - pw2, x12 = px + pw2;
    float y11 = py - ph2, y12 = py + ph2;
    float x21 = tx - tw2, x22 = tx + tw2;
    float y21 = ty - th2, y22 = ty + th2;
    float iw = fmaxf(fminf(x12, x22) - fmaxf(x11, x21), 0.0f);
    float ih = fmaxf(fminf(y12, y22) - fmaxf(y11, y21), 0.0f);
    float inter = iw * ih;
    float a1 = (x12 - x11) * (y12 - y11);
    float a2 = (x22 - x21) * (y22 - y21);
    return inter / (a1 + a2 - inter + 1e-7f);
}

__global__ void __launch_bounds__(192, 1) dl_fused_kernel(
    const float* __restrict__ p3,
    const float* __restrict__ p4,
    const float* __restrict__ p5,
    const int*   __restrict__ tcls,
    const float* __restrict__ tbox,
    float*       __restrict__ out)
{
    const int b   = blockIdx.x;
    const int t   = threadIdx.x;
    const int s   = t >> 6;     // scale 0..2
    const int tid = t & 63;     // 0..63 within scale group

    const float* pred;
    int W;
    if      (s == 0) { pred = p3; W = 160; }
    else if (s == 1) { pred = p4; W = 80;  }
    else             { pred = p5; W = 40;  }

    __shared__ int4  s_pk4[3][15];          // packed (cell<<6)|cls, 60 per scale
    __shared__ float s_red[3][2][4];        // per-scale 2-warp partials
    __shared__ float s_fin[2][12];          // finalize cross-warp
    __shared__ int   s_last;

    float tx = 0.f, ty = 0.f, tw = 0.f, th = 0.f;
    int   cell = -1;
    float z[NCLS], px = 0.f, py = 0.f, pw = 0.f, ph = 0.f;

    if (tid < NT) {
        int   cls = tcls[b * NT + tid];
        float4 bx = reinterpret_cast<const float4*>(tbox)[b * NT + tid];
        tx = bx.x; ty = bx.y; tw = bx.z; th = bx.w;
        int gx = (int)(tx * (float)W); gx = min(max(gx, 0), W - 1);
        int gy = (int)(ty * (float)W); gy = min(max(gy, 0), W - 1);
        cell = gy * W + gx;
        reinterpret_cast<int*>(&s_pk4[s][0])[tid] = (cell << 6) | cls;

        // Issue all 10 scattered pred loads up front (MLP=10, overlaps scan).
        const size_t HW   = (size_t)W * (size_t)W;
        const float* base = pred + (size_t)b * NCH * HW + (size_t)cell;
        #pragma unroll
        for (int c = 0; c < NCLS; ++c) z[c] = __ldg(base + (size_t)c * HW);
        px = __ldg(base + (size_t)7  * HW);
        py = __ldg(base + (size_t)8  * HW);
        pw = __ldg(base + (size_t)9  * HW);
        ph = __ldg(base + (size_t)10 * HW);
    }
    __syncthreads();

    float cls_p = 0.0f, iou_p = 0.0f, inner_p = 0.0f, np = 0.0f;

    if (tid < NT) {
        // Register-resident scan over all 60 packed entries (broadcast LDS.128).
        const int cellsh = cell << 6;
        unsigned cm   = 0u;     // union of one-hot classes at this cell
        int      bad  = 0;      // some later target claims this cell
        #pragma unroll
        for (int i = 0; i < 15; ++i) {
            int4 q = s_pk4[s][i];
            int idx = i * 4;
            {
                int m = (((q.x ^ cellsh) & ~63) == 0);
                if (m) { cm |= 1u << (q.x & 63); bad |= (idx + 0 > tid); }
            }
            {
                int m = (((q.y ^ cellsh) & ~63) == 0);
                if (m) { cm |= 1u << (q.y & 63); bad |= (idx + 1 > tid); }
            }
            {
                int m = (((q.z ^ cellsh) & ~63) == 0);
                if (m) { cm |= 1u << (q.z & 63); bad |= (idx + 2 > tid); }
            }
            {
                int m = (((q.w ^ cellsh) & ~63) == 0);
                if (m) { cm |= 1u << (q.w & 63); bad |= (idx + 3 > tid); }
            }
        }

        if (!bad) {   // owner = last target mapping to this cell
            float bce = 0.0f;
            #pragma unroll
            for (int c = 0; c < NCLS; ++c) {
                float tt = ((cm >> c) & 1u) ? 1.0f : 0.0f;
                bce += fmaxf(z[c], 0.0f) - z[c] * tt + log1pf(expf(-fabsf(z[c])));
            }
            float iou   = iou_scaled(px, py, pw, ph, tx, ty, tw, th, 1.0f);
            float inner = iou_scaled(px, py, pw, ph, tx, ty, tw, th, 0.7f);
            cls_p = bce;  iou_p = 1.0f - iou;  inner_p = 1.0f - inner;  np = 1.0f;
        }
    }

    // Per-scale reduction: warp shfl, then combine the scale's 2 warps.
    #pragma unroll
    for (int o = 16; o > 0; o >>= 1) {
        cls_p   += __shfl_down_sync(0xffffffffu, cls_p,   o);
        iou_p   += __shfl_down_sync(0xffffffffu, iou_p,   o);
        inner_p += __shfl_down_sync(0xffffffffu, inner_p, o);
        np      += __shfl_down_sync(0xffffffffu, np,      o);
    }
    const int wInS = (tid >> 5);   // warp index within scale group (0/1)
    if ((tid & 31) == 0) {
        s_red[s][wInS][0] = cls_p;  s_red[s][wInS][1] = iou_p;
        s_red[s][wInS][2] = inner_p; s_red[s][wInS][3] = np;
    }
    __syncthreads();

    // One writer thread per scale: 4 contention-free STGs + own fence.
    if (tid == 0) {
        #pragma unroll
        for (int k = 0; k < 4; ++k)
            g_part[b][s * 4 + k] = s_red[s][0][k] + s_red[s][1][k];
        __threadfence();
    }
    __syncthreads();

    if (t == 0) {
        unsigned d = atomicAdd(&g_done, 1u);
        s_last = (d == NB - 1);
    }
    __syncthreads();

    if (s_last) {
        // All prior blocks' g_part writes are fenced before their counter
        // bump; we observed the final count, so L2 holds them. Volatile
        // loads bypass L1.
        float m[12];
        #pragma unroll
        for (int k = 0; k < 12; ++k) m[k] = 0.0f;
        if (t < NB) {
            const volatile float* row = g_part[t];
            #pragma unroll
            for (int k = 0; k < 12; ++k) m[k] = row[k];
        }
        #pragma unroll
        for (int o = 16; o > 0; o >>= 1) {
            #pragma unroll
            for (int k = 0; k < 12; ++k)
                m[k] += __shfl_down_sync(0xffffffffu, m[k], o);
        }
        const int w = t >> 5;
        if (w < 2 && (t & 31) == 0) {
            #pragma unroll
            for (int k = 0; k < 12; ++k) s_fin[w][k] = m[k];
        }
        __syncthreads();
        if (t == 0) {
            float cls_total = 0.0f, box_total = 0.0f;
            #pragma unroll
            for (int k2 = 0; k2 < 3; ++k2) {
                float csum  = s_fin[0][k2 * 4 + 0] + s_fin[1][k2 * 4 + 0];
                float isum  = s_fin[0][k2 * 4 + 1] + s_fin[1][k2 * 4 + 1];
                float insum = s_fin[0][k2 * 4 + 2] + s_fin[1][k2 * 4 + 2];
                float npos  = s_fin[0][k2 * 4 + 3] + s_fin[1][k2 * 4 + 3];
                float inv = 1.0f / (npos + 1e-8f);
                cls_total += csum * inv;
                // box = 0.5*iou + 0.5*(0.5*iou + 0.5*inner)
                box_total += 0.75f * (isum * inv) + 0.25f * (insum * inv);
            }
            cls_total *= (1.0f / 3.0f);
            box_total *= (1.0f / 3.0f);
            out[0] = 0.5f * cls_total + 7.5f * box_total;  // CLS_W, BOX_W
            out[1] = cls_total;
            out[2] = box_total;
            atomicExch(&g_done, 0u);   // reset for next graph replay
        }
    }
}

extern "C" void kernel_launch(void* const* d_in, const int* in_sizes, int n_in,
                              void* d_out, int out_size)
{
    const float* p3   = (const float*)d_in[0];
    const float* p4   = (const float*)d_in[1];
    const float* p5   = (const float*)d_in[2];
    const int*   tcls = (const int*)  d_in[3];
    const float* tbox = (const float*)d_in[4];
    float*       out  = (float*)d_out;

    dl_fused_kernel<<<NB, 192>>>(p3, p4, p5, tcls, tbox, out);
}

// round 6
// speedup vs baseline: 5.0318x; 1.1837x over previous
#include <cuda_runtime.h>
#include <cuda_bf16.h>

// DetectionLoss, single fused kernel, v4.
// Grid: (64 batches x 3 scales) = 192 blocks x 64 threads — spreads the
// scattered pred gather (the per-SM L1tex bottleneck) across 3x more SMs
// than v3. Register-resident collision scan; contention-free partial-sum
// writes + parallel last-block finalize (no accumulator atomics).

#define NCH   11
#define NCLS  6
#define NT    60
#define NB    64
#define NBLK  (NB * 3)

__device__ float    g_part[NB][12];   // [batch][scale*4 + {cls,iou,inner,np}]
__device__ unsigned g_done;

__device__ __forceinline__ float iou_scaled(
    float px, float py, float pw, float ph,
    float tx, float ty, float tw, float th, float sc)
{
    float pw2 = pw * sc * 0.5f, ph2 = ph * sc * 0.5f;
    float tw2 = tw * sc * 0.5f, th2 = th * sc * 0.5f;
    float x11 = px - pw2, x12 = px + pw2;
    float y11 = py - ph2, y12 = py + ph2;
    float x21 = tx - tw2, x22 = tx + tw2;
    float y21 = ty - th2, y22 = ty + th2;
    float iw = fmaxf(fminf(x12, x22) - fmaxf(x11, x21), 0.0f);
    float ih = fmaxf(fminf(y12, y22) - fmaxf(y11, y21), 0.0f);
    float inter = iw * ih;
    float a1 = (x12 - x11) * (y12 - y11);
    float a2 = (x22 - x21) * (y22 - y21);
    return inter / (a1 + a2 - inter + 1e-7f);
}

__global__ void __launch_bounds__(64, 16) dl_fused_kernel(
    const float* __restrict__ p3,
    const float* __restrict__ p4,
    const float* __restrict__ p5,
    const int*   __restrict__ tcls,
    const float* __restrict__ tbox,
    float*       __restrict__ out)
{
    const int b   = blockIdx.x;
    const int s   = blockIdx.y;
    const int tid = threadIdx.x;

    const float* pred;
    int W;
    if      (s == 0) { pred = p3; W = 160; }
    else if (s == 1) { pred = p4; W = 80;  }
    else             { pred = p5; W = 40;  }

    __shared__ int4  s_pk4[15];      // packed (cell<<6)|cls, 60 entries
    __shared__ float s_red[2][4];    // 2-warp partials
    __shared__ float s_fin[2][12];   // finalize cross-warp
    __shared__ int   s_last;

    float tx = 0.f, ty = 0.f, tw = 0.f, th = 0.f;
    int   cell = -1;
    float z[NCLS], px = 0.f, py = 0.f, pw = 0.f, ph = 0.f;

    if (tid < NT) {
        int   cls = tcls[b * NT + tid];
        float4 bx = reinterpret_cast<const float4*>(tbox)[b * NT + tid];
        tx = bx.x; ty = bx.y; tw = bx.z; th = bx.w;
        int gx = (int)(tx * (float)W); gx = min(max(gx, 0), W - 1);
        int gy = (int)(ty * (float)W); gy = min(max(gy, 0), W - 1);
        cell = gy * W + gx;
        reinterpret_cast<int*>(&s_pk4[0])[tid] = (cell << 6) | cls;

        // All 10 scattered pred loads issued up front (MLP=10, overlap scan).
        const size_t HW   = (size_t)W * (size_t)W;
        const float* base = pred + (size_t)b * NCH * HW + (size_t)cell;
        #pragma unroll
        for (int c = 0; c < NCLS; ++c) z[c] = __ldg(base + (size_t)c * HW);
        px = __ldg(base + (size_t)7  * HW);
        py = __ldg(base + (size_t)8  * HW);
        pw = __ldg(base + (size_t)9  * HW);
        ph = __ldg(base + (size_t)10 * HW);
    }
    __syncthreads();

    float cls_p = 0.0f, iou_p = 0.0f, inner_p = 0.0f, np = 0.0f;

    if (tid < NT) {
        // Register-resident scan over all 60 packed entries (broadcast LDS.128).
        const int cellsh = cell << 6;
        unsigned cm  = 0u;   // union of one-hot classes at this cell
        int      bad = 0;    // some later target claims this cell
        #pragma unroll
        for (int i = 0; i < 15; ++i) {
            int4 q = s_pk4[i];
            int idx = i * 4;
            if (((q.x ^ cellsh) & ~63) == 0) { cm |= 1u << (q.x & 63); bad |= (idx + 0 > tid); }
            if (((q.y ^ cellsh) & ~63) == 0) { cm |= 1u << (q.y & 63); bad |= (idx + 1 > tid); }
            if (((q.z ^ cellsh) & ~63) == 0) { cm |= 1u << (q.z & 63); bad |= (idx + 2 > tid); }
            if (((q.w ^ cellsh) & ~63) == 0) { cm |= 1u << (q.w & 63); bad |= (idx + 3 > tid); }
        }

        if (!bad) {   // owner = last target mapping to this cell
            float bce = 0.0f;
            #pragma unroll
            for (int c = 0; c < NCLS; ++c) {
                float tt = ((cm >> c) & 1u) ? 1.0f : 0.0f;
                bce += fmaxf(z[c], 0.0f) - z[c] * tt + log1pf(expf(-fabsf(z[c])));
            }
            float iou   = iou_scaled(px, py, pw, ph, tx, ty, tw, th, 1.0f);
            float inner = iou_scaled(px, py, pw, ph, tx, ty, tw, th, 0.7f);
            cls_p = bce;  iou_p = 1.0f - iou;  inner_p = 1.0f - inner;  np = 1.0f;
        }
    }

    // Warp shfl reduce, combine 2 warps in smem.
    #pragma unroll
    for (int o = 16; o > 0; o >>= 1) {
        cls_p   += __shfl_down_sync(0xffffffffu, cls_p,   o);
        iou_p   += __shfl_down_sync(0xffffffffu, iou_p,   o);
        inner_p += __shfl_down_sync(0xffffffffu, inner_p, o);
        np      += __shfl_down_sync(0xffffffffu, np,      o);
    }
    const int warp = tid >> 5;
    if ((tid & 31) == 0) {
        s_red[warp][0] = cls_p;  s_red[warp][1] = iou_p;
        s_red[warp][2] = inner_p; s_red[warp][3] = np;
    }
    __syncthreads();

    // Single writer: 4 contention-free STGs (disjoint 16B slice of row b),
    // fence, then bump the done counter.
    if (tid == 0) {
        #pragma unroll
        for (int k = 0; k < 4; ++k)
            g_part[b][s * 4 + k] = s_red[0][k] + s_red[1][k];
        __threadfence();
        unsigned d = atomicAdd(&g_done, 1u);
        s_last = (d == NBLK - 1);
    }
    __syncthreads();

    if (s_last) {
        // All prior blocks fenced their g_part writes before bumping the
        // counter; we observed the final count, so L2 holds them. Volatile
        // loads bypass L1.
        float m[12];
        #pragma unroll
        for (int k = 0; k < 12; ++k) m[k] = 0.0f;
        {
            const volatile float* row = g_part[tid];   // tid < 64 == NB
            #pragma unroll
            for (int k = 0; k < 12; ++k) m[k] = row[k];
        }
        #pragma unroll
        for (int o = 16; o > 0; o >>= 1) {
            #pragma unroll
            for (int k = 0; k < 12; ++k)
                m[k] += __shfl_down_sync(0xffffffffu, m[k], o);
        }
        const int w = tid >> 5;
        if ((tid & 31) == 0) {
            #pragma unroll
            for (int k = 0; k < 12; ++k) s_fin[w][k] = m[k];
        }
        __syncthreads();
        if (tid == 0) {
            float cls_total = 0.0f, box_total = 0.0f;
            #pragma unroll
            for (int k2 = 0; k2 < 3; ++k2) {
                float csum  = s_fin[0][k2 * 4 + 0] + s_fin[1][k2 * 4 + 0];
                float isum  = s_fin[0][k2 * 4 + 1] + s_fin[1][k2 * 4 + 1];
                float insum = s_fin[0][k2 * 4 + 2] + s_fin[1][k2 * 4 + 2];
                float npos  = s_fin[0][k2 * 4 + 3] + s_fin[1][k2 * 4 + 3];
                float inv = 1.0f / (npos + 1e-8f);
                cls_total += csum * inv;
                // box = 0.5*iou + 0.5*(0.5*iou + 0.5*inner)
                box_total += 0.75f * (isum * inv) + 0.25f * (insum * inv);
            }
            cls_total *= (1.0f / 3.0f);
            box_total *= (1.0f / 3.0f);
            out[0] = 0.5f * cls_total + 7.5f * box_total;  // CLS_W, BOX_W
            out[1] = cls_total;
            out[2] = box_total;
            atomicExch(&g_done, 0u);   // reset for next graph replay
        }
    }
}

extern "C" void kernel_launch(void* const* d_in, const int* in_sizes, int n_in,
                              void* d_out, int out_size)
{
    const float* p3   = (const float*)d_in[0];
    const float* p4   = (const float*)d_in[1];
    const float* p5   = (const float*)d_in[2];
    const int*   tcls = (const int*)  d_in[3];
    const float* tbox = (const float*)d_in[4];
    float*       out  = (float*)d_out;

    dim3 grid(NB, 3);
    dl_fused_kernel<<<grid, 64>>>(p3, p4, p5, tcls, tbox, out);
}

// round 7
// speedup vs baseline: 5.2353x; 1.0404x over previous
#include <cuda_runtime.h>
#include <cuda_bf16.h>

// DetectionLoss, single fused kernel, v5.
// Grid (64 batches x 3 scales) x 64 threads. Sparse evaluation with
// register-resident collision scan. v5: hierarchical completion counters
// (per-batch padded counters -> root) to kill the contended single-address
// atomic tail; 32-bit gather addressing; fast-math BCE.

#define NCH   11
#define NCLS  6
#define NT    60
#define NB    64

__device__ float    g_part[NB][12];        // [batch][scale*4 + {cls,iou,inner,np}]
__device__ unsigned g_done1[NB][32];       // per-batch counter, 128B padded
__device__ unsigned g_done2;               // root counter (NB arrivals)

__device__ __forceinline__ float iou_scaled(
    float px, float py, float pw, float ph,
    float tx, float ty, float tw, float th, float sc)
{
    float pw2 = pw * sc * 0.5f, ph2 = ph * sc * 0.5f;
    float tw2 = tw * sc * 0.5f, th2 = th * sc * 0.5f;
    float x11 = px - pw2, x12 = px + pw2;
    float y11 = py - ph2, y12 = py + ph2;
    float x21 = tx - tw2, x22 = tx + tw2;
    float y21 = ty - th2, y22 = ty + th2;
    float iw = fmaxf(fminf(x12, x22) - fmaxf(x11, x21), 0.0f);
    float ih = fmaxf(fminf(y12, y22) - fmaxf(y11, y21), 0.0f);
    float inter = iw * ih;
    float a1 = (x12 - x11) * (y12 - y11);
    float a2 = (x22 - x21) * (y22 - y21);
    return inter / (a1 + a2 - inter + 1e-7f);
}

__global__ void __launch_bounds__(64, 16) dl_fused_kernel(
    const float* __restrict__ p3,
    const float* __restrict__ p4,
    const float* __restrict__ p5,
    const int*   __restrict__ tcls,
    const float* __restrict__ tbox,
    float*       __restrict__ out)
{
    const int b   = blockIdx.x;
    const int s   = blockIdx.y;
    const int tid = threadIdx.x;

    const float* pred;
    int W;
    if      (s == 0) { pred = p3; W = 160; }
    else if (s == 1) { pred = p4; W = 80;  }
    else             { pred = p5; W = 40;  }

    __shared__ int4  s_pk4[15];      // packed (cell<<6)|cls, 60 entries
    __shared__ float s_red[2][4];    // 2-warp partials
    __shared__ float s_fin[2][12];   // finalize cross-warp
    __shared__ int   s_last;

    float tx = 0.f, ty = 0.f, tw = 0.f, th = 0.f;
    int   cell = -1;
    float z[NCLS], px = 0.f, py = 0.f, pw = 0.f, ph = 0.f;

    if (tid < NT) {
        int   cls = tcls[b * NT + tid];
        float4 bx = reinterpret_cast<const float4*>(tbox)[b * NT + tid];
        tx = bx.x; ty = bx.y; tw = bx.z; th = bx.w;
        int gx = (int)(tx * (float)W); gx = min(max(gx, 0), W - 1);
        int gy = (int)(ty * (float)W); gy = min(max(gy, 0), W - 1);
        cell = gy * W + gx;
        reinterpret_cast<int*>(&s_pk4[0])[tid] = (cell << 6) | cls;

        // 32-bit offsets (max index < 2^25) -> short IMAD chains, dense LDGs.
        const int HW = W * W;
        const float* base = pred + b * NCH * HW + cell;
        #pragma unroll
        for (int c = 0; c < NCLS; ++c) z[c] = __ldg(base + c * HW);
        px = __ldg(base + 7  * HW);
        py = __ldg(base + 8  * HW);
        pw = __ldg(base + 9  * HW);
        ph = __ldg(base + 10 * HW);
    }
    __syncthreads();

    float cls_p = 0.0f, iou_p = 0.0f, inner_p = 0.0f, np = 0.0f;

    if (tid < NT) {
        // Register-resident scan over all 60 packed entries (broadcast LDS.128).
        const int cellsh = cell << 6;
        unsigned cm  = 0u;   // union of one-hot classes at this cell
        int      bad = 0;    // some later target claims this cell
        #pragma unroll
        for (int i = 0; i < 15; ++i) {
            int4 q = s_pk4[i];
            int idx = i * 4;
            if (((q.x ^ cellsh) & ~63) == 0) { cm |= 1u << (q.x & 63); bad |= (idx + 0 > tid); }
            if (((q.y ^ cellsh) & ~63) == 0) { cm |= 1u << (q.y & 63); bad |= (idx + 1 > tid); }
            if (((q.z ^ cellsh) & ~63) == 0) { cm |= 1u << (q.z & 63); bad |= (idx + 2 > tid); }
            if (((q.w ^ cellsh) & ~63) == 0) { cm |= 1u << (q.w & 63); bad |= (idx + 3 > tid); }
        }

        if (!bad) {   // owner = last target mapping to this cell
            float bce = 0.0f;
            #pragma unroll
            for (int c = 0; c < NCLS; ++c) {
                float tt = ((cm >> c) & 1u) ? 1.0f : 0.0f;
                // fast-math: abs err ~1e-6 << 1e-3 tolerance
                bce += fmaxf(z[c], 0.0f) - z[c] * tt
                     + __logf(1.0f + __expf(-fabsf(z[c])));
            }
            float iou   = iou_scaled(px, py, pw, ph, tx, ty, tw, th, 1.0f);
            float inner = iou_scaled(px, py, pw, ph, tx, ty, tw, th, 0.7f);
            cls_p = bce;  iou_p = 1.0f - iou;  inner_p = 1.0f - inner;  np = 1.0f;
        }
    }

    // Warp shfl reduce, combine the 2 warps in smem.
    #pragma unroll
    for (int o = 16; o > 0; o >>= 1) {
        cls_p   += __shfl_down_sync(0xffffffffu, cls_p,   o);
        iou_p   += __shfl_down_sync(0xffffffffu, iou_p,   o);
        inner_p += __shfl_down_sync(0xffffffffu, inner_p, o);
        np      += __shfl_down_sync(0xffffffffu, np,      o);
    }
    const int warp = tid >> 5;
    if ((tid & 31) == 0) {
        s_red[warp][0] = cls_p;  s_red[warp][1] = iou_p;
        s_red[warp][2] = inner_p; s_red[warp][3] = np;
    }
    __syncthreads();

    // Partials out + hierarchical completion:
    //   level 1: per-batch counter (3 arrivals, 64 counters in parallel)
    //   level 2: root counter (64 arrivals)
    if (tid == 0) {
        #pragma unroll
        for (int k = 0; k < 4; ++k)
            g_part[b][s * 4 + k] = s_red[0][k] + s_red[1][k];
        __threadfence();
        int lastflag = 0;
        unsigned d1 = atomicAdd(&g_done1[b][0], 1u);
        if (d1 == 2u) {                       // batch-last block
            atomicExch(&g_done1[b][0], 0u);   // reset own counter (safe: we are 3rd)
            unsigned d2 = atomicAdd(&g_done2, 1u);
            lastflag = (d2 == NB - 1);
        }
        s_last = lastflag;
    }
    __syncthreads();

    if (s_last) {
        // All prior blocks fenced their g_part writes before their counter
        // bumps; we observed the final root count, so L2 holds them.
        float m[12];
        {
            const volatile float* row = g_part[tid];   // tid < 64 == NB
            #pragma unroll
            for (int k = 0; k < 12; ++k) m[k] = row[k];
        }
        #pragma unroll
        for (int o = 16; o > 0; o >>= 1) {
            #pragma unroll
            for (int k = 0; k < 12; ++k)
                m[k] += __shfl_down_sync(0xffffffffu, m[k], o);
        }
        const int w = tid >> 5;
        if ((tid & 31) == 0) {
            #pragma unroll
            for (int k = 0; k < 12; ++k) s_fin[w][k] = m[k];
        }
        __syncthreads();
        if (tid == 0) {
            float cls_total = 0.0f, box_total = 0.0f;
            #pragma unroll
            for (int k2 = 0; k2 < 3; ++k2) {
                float csum  = s_fin[0][k2 * 4 + 0] + s_fin[1][k2 * 4 + 0];
                float isum  = s_fin[0][k2 * 4 + 1] + s_fin[1][k2 * 4 + 1];
                float insum = s_fin[0][k2 * 4 + 2] + s_fin[1][k2 * 4 + 2];
                float npos  = s_fin[0][k2 * 4 + 3] + s_fin[1][k2 * 4 + 3];
                float inv = 1.0f / (npos + 1e-8f);
                cls_total += csum * inv;
                // box = 0.5*iou + 0.5*(0.5*iou + 0.5*inner)
                box_total += 0.75f * (isum * inv) + 0.25f * (insum * inv);
            }
            cls_total *= (1.0f / 3.0f);
            box_total *= (1.0f / 3.0f);
            out[0] = 0.5f * cls_total + 7.5f * box_total;  // CLS_W, BOX_W
            out[1] = cls_total;
            out[2] = box_total;
            atomicExch(&g_done2, 0u);   // reset root for next graph replay
        }
    }
}

extern "C" void kernel_launch(void* const* d_in, const int* in_sizes, int n_in,
                              void* d_out, int out_size)
{
    const float* p3   = (const float*)d_in[0];
    const float* p4   = (const float*)d_in[1];
    const float* p5   = (const float*)d_in[2];
    const int*   tcls = (const int*)  d_in[3];
    const float* tbox = (const float*)d_in[4];
    float*       out  = (float*)d_out;

    dim3 grid(NB, 3);
    dl_fused_kernel<<<grid, 64>>>(p3, p4, p5, tcls, tbox, out);
}